// round 13
// baseline (speedup 1.0000x reference)
#include <cuda_runtime.h>
#include <math.h>

// Problem constants (B=4, S=4096, D=2048, E=8, K=2)
#define NTOK    16384
#define DIM     2048
#define NEXP    8
#define NASSIGN (NTOK*2)       // 32768
#define CAP     5120           // int(NTOK*2/8 * 1.25)
#define NTASK   (NTOK/4)       // 4096 tasks of 4 tokens
#define NBLK    296            // persistent: 2 blocks per SM
#define W_BYTES (NEXP*DIM*4)   // 64 KB

// Output layout (float32): [0,32768) indices | [32768,65536) weights |
// [65536] loss | [65537,98305) mask

// Scratch: __device__ globals (zero-init at load; last block resets so every
// graph replay sees zeros).
__device__ int      g_cnt[NEXP];
__device__ float    g_probsum[NEXP];
__device__ unsigned g_done;
__device__ unsigned g_ticket;
__device__ unsigned long long g_bucket[NEXP][NASSIGN];

// Packed fp32x2 FMA (Blackwell): d = a*b + d on two f32 lanes (dim pairs).
__device__ __forceinline__ void ffma2(unsigned long long& d,
                                      unsigned long long a,
                                      unsigned long long b) {
    asm("fma.rn.f32x2 %0, %1, %2, %0;" : "+l"(d) : "l"(a), "l"(b));
}
__device__ __forceinline__ float unpack_sum(unsigned long long v) {
    unsigned lo, hi;
    asm("mov.b64 {%0, %1}, %2;" : "=r"(lo), "=r"(hi) : "l"(v));
    return __uint_as_float(lo) + __uint_as_float(hi);
}
// Warp-collective ticket grab (lane 0 atomic, broadcast).
__device__ __forceinline__ int grab_task(int lane) {
    int t = 0;
    if (lane == 0) t = (int)atomicAdd(&g_ticket, 1u);
    return __shfl_sync(0xffffffffu, t, 0);
}

// Persistent fused kernel. Each warp pulls 4-token tasks from a global
// ticket. Hot loop is software-pipelined at chunk granularity: issue next
// chunk's 4 LDG.128, then compute the current chunk (8 LDS.128 + 32 FFMA2).
// Straight-line (fully unrolled), no predication, plain loads.
// LAST arriving block computes loss + (rare) capacity drop + resets scratch.
__global__ __launch_bounds__(256, 2)
void router_main(const float* __restrict__ x,
                 const float* __restrict__ wg,
                 float* __restrict__ out) {
    extern __shared__ float sw[];              // 8*2048 f32 = 64 KB
    __shared__ float s_prob[NEXP];
    __shared__ int   s_last;

    const int tid  = threadIdx.x;
    const int lane = tid & 31;
    if (tid < NEXP) s_prob[tid] = 0.0f;

    // stage w_gate into shared ONCE per persistent block
    {
        float4* sw4 = (float4*)sw;
        const float4* wg4 = (const float4*)wg;
        #pragma unroll
        for (int i = tid; i < NEXP * DIM / 4; i += 256) sw4[i] = wg4[i];
    }
    __syncthreads();
    const ulonglong2* sw2 = (const ulonglong2*)sw;

    int task = grab_task(lane);
    while (task < NTASK) {
        const int tok0 = task * 4;
        const ulonglong2* xr0 = (const ulonglong2*)(x + (size_t)tok0 * DIM);
        const ulonglong2* xr1 = (const ulonglong2*)(x + (size_t)(tok0 + 1) * DIM);
        const ulonglong2* xr2 = (const ulonglong2*)(x + (size_t)(tok0 + 2) * DIM);
        const ulonglong2* xr3 = (const ulonglong2*)(x + (size_t)(tok0 + 3) * DIM);

        unsigned long long acc[4][NEXP];
        #pragma unroll
        for (int t = 0; t < 4; t++)
            #pragma unroll
            for (int e = 0; e < NEXP; e++) acc[t][e] = 0ull;

        // prologue: load chunk 0
        ulonglong2 cur0 = xr0[lane];
        ulonglong2 cur1 = xr1[lane];
        ulonglong2 cur2 = xr2[lane];
        ulonglong2 cur3 = xr3[lane];

        int next = grab_task(lane);   // ATOMG latency hidden under compute

        // steady state: load chunk c+1, compute chunk c  (fully unrolled)
        #pragma unroll
        for (int c = 0; c < 15; c++) {
            const int cn = (c + 1) * 32 + lane;
            ulonglong2 nxt0 = xr0[cn];
            ulonglong2 nxt1 = xr1[cn];
            ulonglong2 nxt2 = xr2[cn];
            ulonglong2 nxt3 = xr3[cn];

            const int cc = c * 32 + lane;
            #pragma unroll
            for (int e = 0; e < NEXP; e++) {
                ulonglong2 wv = sw2[e * (DIM / 4) + cc];
                ffma2(acc[0][e], cur0.x, wv.x); ffma2(acc[0][e], cur0.y, wv.y);
                ffma2(acc[1][e], cur1.x, wv.x); ffma2(acc[1][e], cur1.y, wv.y);
                ffma2(acc[2][e], cur2.x, wv.x); ffma2(acc[2][e], cur2.y, wv.y);
                ffma2(acc[3][e], cur3.x, wv.x); ffma2(acc[3][e], cur3.y, wv.y);
            }
            cur0 = nxt0; cur1 = nxt1; cur2 = nxt2; cur3 = nxt3;
        }
        // epilogue chunk 15
        {
            const int cc = 15 * 32 + lane;
            #pragma unroll
            for (int e = 0; e < NEXP; e++) {
                ulonglong2 wv = sw2[e * (DIM / 4) + cc];
                ffma2(acc[0][e], cur0.x, wv.x); ffma2(acc[0][e], cur0.y, wv.y);
                ffma2(acc[1][e], cur1.x, wv.x); ffma2(acc[1][e], cur1.y, wv.y);
                ffma2(acc[2][e], cur2.x, wv.x); ffma2(acc[2][e], cur2.y, wv.y);
                ffma2(acc[3][e], cur3.x, wv.x); ffma2(acc[3][e], cur3.y, wv.y);
            }
        }

        // Collapse f32x2 halves, butterfly so lanes 0-3 hold full logits.
        float logit[4][NEXP];
        #pragma unroll
        for (int t = 0; t < 4; t++)
            #pragma unroll
            for (int e = 0; e < NEXP; e++) {
                float v = unpack_sum(acc[t][e]);
                v += __shfl_xor_sync(0xffffffffu, v, 16);
                v += __shfl_xor_sync(0xffffffffu, v, 8);
                v += __shfl_xor_sync(0xffffffffu, v, 4);
                v += __shfl_xor_sync(0xffffffffu, v, 2);
                v += __shfl_xor_sync(0xffffffffu, v, 1);
                logit[t][e] = v;
            }

        if (lane < 4) {
            int token = tok0 + lane;
            float p[NEXP];
            float m = logit[lane][0];
            #pragma unroll
            for (int e = 1; e < NEXP; e++) m = fmaxf(m, logit[lane][e]);
            float s = 0.0f;
            #pragma unroll
            for (int e = 0; e < NEXP; e++) { p[e] = expf(logit[lane][e] - m); s += p[e]; }
            float inv = 1.0f / s;
            #pragma unroll
            for (int e = 0; e < NEXP; e++) p[e] *= inv;

            // top-2, ties -> lowest index
            int i1 = 0; float b1 = p[0];
            #pragma unroll
            for (int e = 1; e < NEXP; e++) if (p[e] > b1) { b1 = p[e]; i1 = e; }
            int i2 = -1; float b2 = -1.0f;
            #pragma unroll
            for (int e = 0; e < NEXP; e++) if (e != i1 && p[e] > b2) { b2 = p[e]; i2 = e; }

            float ssum = b1 + b2;
            float w1 = b1 / ssum, w2 = b2 / ssum;

            int n0 = token * 2;
            out[n0]     = (float)i1;
            out[n0 + 1] = (float)i2;
            out[NASSIGN + n0]     = w1;
            out[NASSIGN + n0 + 1] = w2;
            out[2 * NASSIGN + 1 + n0]     = 1.0f;
            out[2 * NASSIGN + 1 + n0 + 1] = 1.0f;

            // per-expert bucket append; keys order-independent
            int s1 = atomicAdd(&g_cnt[i1], 1);
            g_bucket[i1][s1] = ((unsigned long long)__float_as_uint(w1) << 32) |
                               (unsigned)(~(unsigned)n0);
            int s2 = atomicAdd(&g_cnt[i2], 1);
            g_bucket[i2][s2] = ((unsigned long long)__float_as_uint(w2) << 32) |
                               (unsigned)(~(unsigned)(n0 + 1));

            #pragma unroll
            for (int e = 0; e < NEXP; e++) atomicAdd(&s_prob[e], p[e]);
        }
        task = next;
    }

    // flush block-accumulated prob sums
    __syncthreads();
    if (tid < NEXP) atomicAdd(&g_probsum[tid], s_prob[tid]);
    __syncthreads();

    // ---- arrival counter: last block finalizes ----
    if (tid == 0) {
        __threadfence();
        unsigned old = atomicAdd(&g_done, 1u);
        s_last = (old == (unsigned)(gridDim.x - 1)) ? 1 : 0;
    }
    __syncthreads();
    if (!s_last) return;

    __shared__ int cnt[NEXP];
    if (tid < NEXP) cnt[tid] = __ldcg(&g_cnt[tid]);
    __syncthreads();

    if (tid == 0) {
        float imp[NEXP], imps = 0.0f;
        #pragma unroll
        for (int e = 0; e < NEXP; e++) { imp[e] = __ldcg(&g_probsum[e]); imps += imp[e]; }
        float loss = 0.0f;
        #pragma unroll
        for (int e = 0; e < NEXP; e++)
            loss += (imp[e] / imps) * ((float)cnt[e] / (float)NASSIGN);
        out[2 * NASSIGN] = (float)NEXP * loss;
    }

    // Capacity drop (rank = #{j: key > key_i}; keep iff rank < CAP). Matches
    // lexsort((-w, expert)) with flat-index tiebreak; rarely triggers
    // (expected per-expert count ~4096 << 5120).
    for (int e = 0; e < NEXP; e++) {
        int c = cnt[e];
        if (c <= CAP) continue;
        for (int i = tid; i < c; i += blockDim.x) {
            unsigned long long ki = __ldcg(&g_bucket[e][i]);
            int rank = 0;
            for (int j = 0; j < c; j++)
                rank += (__ldcg(&g_bucket[e][j]) > ki) ? 1 : 0;
            if (rank >= CAP) {
                unsigned n = ~(unsigned)(ki & 0xffffffffull);
                out[2 * NASSIGN + 1 + n] = 0.0f;
            }
        }
    }
    __syncthreads();

    // reset scratch for the next graph replay
    if (tid < NEXP) { g_cnt[tid] = 0; g_probsum[tid] = 0.0f; }
    if (tid == 0)   { g_done = 0u; g_ticket = 0u; __threadfence(); }
}

extern "C" void kernel_launch(void* const* d_in, const int* in_sizes, int n_in,
                              void* d_out, int out_size) {
    const float* x  = (const float*)d_in[0];
    const float* wg = (const float*)d_in[1];
    float* out = (float*)d_out;
    (void)in_sizes; (void)n_in; (void)out_size;

    cudaFuncSetAttribute(router_main, cudaFuncAttributeMaxDynamicSharedMemorySize,
                         W_BYTES);

    router_main<<<NBLK, 256, W_BYTES>>>(x, wg, out);
}